// round 7
// baseline (speedup 1.0000x reference)
#include <cuda_runtime.h>
#include <math.h>
#include <float.h>
#include <stdint.h>

// Problem constants
#define BB  2
#define NP  2048
#define MP  2048
#define CCH 512
#define KK  16
#define KK1 8
#define KEY 1024
#define HD1 64
#define HD2 128

// Output layout (flattened tuple, in order)
#define OUT_R    0
#define OUT_T    18
#define OUT_SKP  24
#define OUT_TKP  (OUT_SKP  + BB*3*KEY)        // 6168
#define OUT_SKNN (OUT_TKP  + BB*3*KEY)        // 12312
#define OUT_TKNN (OUT_SKNN + BB*3*KEY*KK)     // 110616
#define OUT_LOSS (OUT_TKNN + BB*3*KEY*KK)     // 208920

// Scratch (static device globals; no allocation at runtime)
__device__ float d_dist[BB*NP*MP];
__device__ float d_Xhi[BB*CCH*NP];
__device__ float d_Xlo[BB*CCH*NP];
__device__ float d_Yhi[BB*CCH*MP];
__device__ float d_Ylo[BB*CCH*MP];
__device__ float d_xx[BB*NP];
__device__ float d_yy[BB*MP];
__device__ float d_src_corr[BB*3*NP];
__device__ float d_rowmax[BB*NP];
__device__ float d_smax[BB*NP];
__device__ float d_weight[BB*NP];
__device__ int   d_topi[BB*KEY];
__device__ float d_Rm[BB*9];
__device__ float d_tv[BB*3];

__device__ __forceinline__ void split_tf32(float x, uint32_t& hi, uint32_t& lo) {
    asm("cvt.rna.tf32.f32 %0, %1;" : "=r"(hi) : "f"(x));
    float r = x - __uint_as_float(hi);
    asm("cvt.rna.tf32.f32 %0, %1;" : "=r"(lo) : "f"(r));
}

// ---------------------------------------------------------------------------
// 1. squared norms of embedding columns (both arrays in one launch)
// ---------------------------------------------------------------------------
__global__ void norms_kernel(const float* __restrict__ X, const float* __restrict__ Y) {
    int idx = blockIdx.x * blockDim.x + threadIdx.x;
    const float* p;
    float* outp;
    if (idx < BB * NP) {
        int b = idx / NP, n = idx % NP;
        p = X + (size_t)b * CCH * NP + n;
        outp = d_xx + idx;
    } else {
        int idy = idx - BB * NP;
        if (idy >= BB * MP) return;
        int b = idy / MP, m = idy % MP;
        p = Y + (size_t)b * CCH * MP + m;
        outp = d_yy + idy;
    }
    float s = 0.f;
    #pragma unroll 8
    for (int c = 0; c < CCH; c++) { float v = p[(size_t)c * NP]; s = fmaf(v, v, s); }
    *outp = s;
}

// ---------------------------------------------------------------------------
// 2a. pre-split X and Y into tf32 hi/lo arrays
// ---------------------------------------------------------------------------
#define XN (BB*CCH*NP)
__global__ void presplit_kernel(const float* __restrict__ X, const float* __restrict__ Y) {
    int idx = blockIdx.x * blockDim.x + threadIdx.x;
    if (idx < XN) {
        uint32_t hi, lo;
        split_tf32(X[idx], hi, lo);
        d_Xhi[idx] = __uint_as_float(hi);
        d_Xlo[idx] = __uint_as_float(lo);
    } else if (idx < 2 * XN) {
        int i = idx - XN;
        uint32_t hi, lo;
        split_tf32(Y[i], hi, lo);
        d_Yhi[i] = __uint_as_float(hi);
        d_Ylo[i] = __uint_as_float(lo);
    }
}

// ---------------------------------------------------------------------------
// 2b. dist GEMM on tensor cores: 3xTF32 mma.sync.m16n8k8, pre-split operands,
//     BK=16, 4 double-buffered tiles (Ahi/Alo/Bhi/Blo), 2 CTAs/SM.
// ---------------------------------------------------------------------------
#define SA 132
#define KSTEP 16
#define STG (KSTEP*SA)          // 2112 floats per tile stage

__device__ __forceinline__ void cp_async16(uint32_t dst, const void* src) {
    asm volatile("cp.async.cg.shared.global [%0], [%1], 16;\n"
                 :: "r"(dst), "l"(src));
}
__device__ __forceinline__ void mma_tf32(float c[4],
                                         uint32_t a0, uint32_t a1, uint32_t a2, uint32_t a3,
                                         uint32_t b0, uint32_t b1) {
    asm volatile("mma.sync.aligned.m16n8k8.row.col.f32.tf32.tf32.f32 "
                 "{%0,%1,%2,%3}, {%4,%5,%6,%7}, {%8,%9}, {%0,%1,%2,%3};"
                 : "+f"(c[0]), "+f"(c[1]), "+f"(c[2]), "+f"(c[3])
                 : "r"(a0), "r"(a1), "r"(a2), "r"(a3), "r"(b0), "r"(b1));
}

extern __shared__ float dynsmem[];

__global__ void __launch_bounds__(256, 2) dist_gemm_tc() {
    int b  = blockIdx.z;
    int n0 = blockIdx.y * 128;
    int m0 = blockIdx.x * 128;
    const float* Xh = d_Xhi + (size_t)b * CCH * NP;
    const float* Xl = d_Xlo + (size_t)b * CCH * NP;
    const float* Yh = d_Yhi + (size_t)b * CCH * MP;
    const float* Yl = d_Ylo + (size_t)b * CCH * MP;
    int tid  = threadIdx.x;
    int w    = tid >> 5;
    int lane = tid & 31;
    int g = lane >> 2;
    int q = lane & 3;
    int wn = w & 1;
    int wm = w >> 1;
    int nbw = wn * 64;
    int mbw = wm * 32;

    // smem: [Ahi s0,s1][Alo s0,s1][Bhi s0,s1][Blo s0,s1], each stage STG floats
    uint32_t sbase = (uint32_t)__cvta_generic_to_shared(dynsmem);

    float c[4][4][4];
    #pragma unroll
    for (int i = 0; i < 4; i++)
        #pragma unroll
        for (int j = 0; j < 4; j++)
            #pragma unroll
            for (int r = 0; r < 4; r++) c[i][j][r] = 0.f;

    // prefetch one BK=16 stage: 4 tiles x 16x128 floats = 2048 float4
    #define PREFETCH(T, S)                                                        \
        {                                                                         \
            int c0_ = (T) * KSTEP;                                                \
            _Pragma("unroll")                                                     \
            for (int i_ = 0; i_ < 8; i_++) {                                      \
                int f_ = tid + i_ * 256;                                          \
                int tile_ = f_ >> 9;                                              \
                int r_ = (f_ >> 5) & 15;                                          \
                int c4_ = (f_ & 31) * 4;                                          \
                const float* src_;                                                \
                if (tile_ == 0)      src_ = Xh + (size_t)(c0_ + r_) * NP + n0 + c4_; \
                else if (tile_ == 1) src_ = Xl + (size_t)(c0_ + r_) * NP + n0 + c4_; \
                else if (tile_ == 2) src_ = Yh + (size_t)(c0_ + r_) * MP + m0 + c4_; \
                else                 src_ = Yl + (size_t)(c0_ + r_) * MP + m0 + c4_; \
                uint32_t d_ = sbase + (uint32_t)(((tile_ * 2 + (S)) * STG + r_ * SA + c4_) * 4); \
                cp_async16(d_, src_);                                             \
            }                                                                     \
            asm volatile("cp.async.commit_group;");                               \
        }

    PREFETCH(0, 0);

    const int NT = CCH / KSTEP;   // 32
    for (int t = 0; t < NT; t++) {
        if (t + 1 < NT) {
            PREFETCH(t + 1, (t + 1) & 1);
            asm volatile("cp.async.wait_group 1;");
        } else {
            asm volatile("cp.async.wait_group 0;");
        }
        __syncthreads();

        int S = t & 1;
        const float* Ahi = dynsmem + (0 * 2 + S) * STG;
        const float* Alo = dynsmem + (1 * 2 + S) * STG;
        const float* Bhi = dynsmem + (2 * 2 + S) * STG;
        const float* Blo = dynsmem + (3 * 2 + S) * STG;

        #pragma unroll
        for (int ks = 0; ks < 2; ks++) {
            int kb = ks * 8;
            uint32_t bh[4][2], bl[4][2];
            #pragma unroll
            for (int j = 0; j < 4; j++) {
                int mb = mbw + j * 8 + g;
                bh[j][0] = *(const uint32_t*)&Bhi[(kb + q) * SA + mb];
                bh[j][1] = *(const uint32_t*)&Bhi[(kb + q + 4) * SA + mb];
                bl[j][0] = *(const uint32_t*)&Blo[(kb + q) * SA + mb];
                bl[j][1] = *(const uint32_t*)&Blo[(kb + q + 4) * SA + mb];
            }
            #pragma unroll
            for (int i = 0; i < 4; i++) {
                int nb = nbw + i * 16 + g;
                uint32_t ah0 = *(const uint32_t*)&Ahi[(kb + q) * SA + nb];
                uint32_t ah1 = *(const uint32_t*)&Ahi[(kb + q) * SA + nb + 8];
                uint32_t ah2 = *(const uint32_t*)&Ahi[(kb + q + 4) * SA + nb];
                uint32_t ah3 = *(const uint32_t*)&Ahi[(kb + q + 4) * SA + nb + 8];
                uint32_t al0 = *(const uint32_t*)&Alo[(kb + q) * SA + nb];
                uint32_t al1 = *(const uint32_t*)&Alo[(kb + q) * SA + nb + 8];
                uint32_t al2 = *(const uint32_t*)&Alo[(kb + q + 4) * SA + nb];
                uint32_t al3 = *(const uint32_t*)&Alo[(kb + q + 4) * SA + nb + 8];
                #pragma unroll
                for (int j = 0; j < 4; j++) {
                    mma_tf32(c[i][j], al0, al1, al2, al3, bh[j][0], bh[j][1]);
                    mma_tf32(c[i][j], ah0, ah1, ah2, ah3, bl[j][0], bl[j][1]);
                    mma_tf32(c[i][j], ah0, ah1, ah2, ah3, bh[j][0], bh[j][1]);
                }
            }
        }
        __syncthreads();
    }
    #undef PREFETCH

    int bN = b * NP, bM = b * MP;
    #pragma unroll
    for (int i = 0; i < 4; i++) {
        int ng0 = n0 + nbw + i * 16 + g;
        int ng1 = ng0 + 8;
        float xv0 = d_xx[bN + ng0];
        float xv1 = d_xx[bN + ng1];
        float* r0 = d_dist + (size_t)(bN + ng0) * MP;
        float* r1 = d_dist + (size_t)(bN + ng1) * MP;
        #pragma unroll
        for (int j = 0; j < 4; j++) {
            int mg = m0 + mbw + j * 8 + 2 * q;
            float y0 = d_yy[bM + mg];
            float y1 = d_yy[bM + mg + 1];
            float2 v0 = make_float2(xv0 - 2.f * c[i][j][0] + y0,
                                    xv0 - 2.f * c[i][j][1] + y1);
            float2 v1 = make_float2(xv1 - 2.f * c[i][j][2] + y0,
                                    xv1 - 2.f * c[i][j][3] + y1);
            *(float2*)(r0 + mg) = v0;
            *(float2*)(r1 + mg) = v1;
        }
    }
}

// ---------------------------------------------------------------------------
// block-sum reduction (shfl + 8-entry combine)
// ---------------------------------------------------------------------------
__device__ __forceinline__ float bred_sumf(float v, float* red8, int tid) {
    #pragma unroll
    for (int o = 16; o > 0; o >>= 1) v += __shfl_down_sync(0xffffffffu, v, o);
    __syncthreads();
    if ((tid & 31) == 0) red8[tid >> 5] = v;
    __syncthreads();
    float r = red8[0];
    #pragma unroll
    for (int i = 1; i < 8; i++) r += red8[i];
    return r;
}

// ---------------------------------------------------------------------------
// 3. fused: per-row score softmaxes -> T -> S -> refined -> rmm softmax ->
//    src_corr GEMV + row max. scores/T/rmm never hit global memory.
// ---------------------------------------------------------------------------
__global__ void rmm_kernel(const int* __restrict__ idx1,
                           const int* __restrict__ idx2,
                           const float* __restrict__ tgt) {
    int row = blockIdx.x;                 // b*NP + n
    int b = row / NP, n = row % NP;
    int tid = threadIdx.x;                // 256
    __shared__ float shT[MP];
    __shared__ float red8[8];
    __shared__ float red4[8][4];

    const int* ip1 = idx1 + (size_t)row * KK1;
    float Tr[8] = {0.f,0.f,0.f,0.f,0.f,0.f,0.f,0.f};
    #pragma unroll 1
    for (int j = 1; j < 8; j++) {
        const float4* dj = (const float4*)(d_dist + ((size_t)b * NP + ip1[j]) * MP);
        float4 v0 = dj[tid];
        float4 v1 = dj[tid + 256];
        float e[8];
        e[0] = __expf(-v0.x); e[1] = __expf(-v0.y);
        e[2] = __expf(-v0.z); e[3] = __expf(-v0.w);
        e[4] = __expf(-v1.x); e[5] = __expf(-v1.y);
        e[6] = __expf(-v1.z); e[7] = __expf(-v1.w);
        float lsum = (e[0] + e[1]) + (e[2] + e[3]) + (e[4] + e[5]) + (e[6] + e[7]);
        float inv = 1.f / bred_sumf(lsum, red8, tid);
        #pragma unroll
        for (int r = 0; r < 8; r++) Tr[r] = fmaf(e[r], inv, Tr[r]);
    }
    float4* shT4 = (float4*)shT;
    shT4[tid]       = make_float4(Tr[0], Tr[1], Tr[2], Tr[3]);
    shT4[tid + 256] = make_float4(Tr[4], Tr[5], Tr[6], Tr[7]);
    __syncthreads();

    const float* drow = d_dist + (size_t)row * MP;
    const int4* i2v = (const int4*)(idx2 + (size_t)b * MP * KK1);
    float r[8];
    float lsum = 0.f;
    #pragma unroll
    for (int it = 0; it < 8; it++) {
        int m = tid + it * 256;
        int4 a = i2v[2 * m], b4 = i2v[2 * m + 1];
        float S = shT[a.y] + shT[a.z] + shT[a.w]
                + shT[b4.x] + shT[b4.y] + shT[b4.z] + shT[b4.w];
        float rr = __expf(1.0f - S * (1.0f / 7.0f)) * drow[m];
        r[it] = __expf(-rr);
        lsum += r[it];
    }
    float inv = 1.f / bred_sumf(lsum, red8, tid);

    const float* t0 = tgt + (size_t)b * 3 * MP;
    float c0 = 0.f, c1 = 0.f, c2 = 0.f, lmax = -FLT_MAX;
    #pragma unroll
    for (int it = 0; it < 8; it++) {
        int m = tid + it * 256;
        float rv = r[it] * inv;
        c0 = fmaf(t0[m], rv, c0);
        c1 = fmaf(t0[MP + m], rv, c1);
        c2 = fmaf(t0[2 * MP + m], rv, c2);
        lmax = fmaxf(lmax, rv);
    }
    #pragma unroll
    for (int o = 16; o > 0; o >>= 1) {
        c0 += __shfl_down_sync(0xffffffffu, c0, o);
        c1 += __shfl_down_sync(0xffffffffu, c1, o);
        c2 += __shfl_down_sync(0xffffffffu, c2, o);
        lmax = fmaxf(lmax, __shfl_down_sync(0xffffffffu, lmax, o));
    }
    __syncthreads();
    if ((tid & 31) == 0) {
        int wid = tid >> 5;
        red4[wid][0] = c0; red4[wid][1] = c1; red4[wid][2] = c2; red4[wid][3] = lmax;
    }
    __syncthreads();
    if (tid == 0) {
        float s0 = 0.f, s1 = 0.f, s2 = 0.f, mx = -FLT_MAX;
        #pragma unroll
        for (int i = 0; i < 8; i++) {
            s0 += red4[i][0]; s1 += red4[i][1]; s2 += red4[i][2];
            mx = fmaxf(mx, red4[i][3]);
        }
        d_src_corr[(b * 3 + 0) * NP + n] = s0;
        d_src_corr[(b * 3 + 1) * NP + n] = s1;
        d_src_corr[(b * 3 + 2) * NP + n] = s2;
        d_rowmax[row] = mx;
    }
}

// ---------------------------------------------------------------------------
// 4. discriminator MLP: all 16 h1 vectors computed up front into smem,
//    then a barrier-free k-loop (W2 row in regs, per-warp shfl partials).
// ---------------------------------------------------------------------------
__global__ void __launch_bounds__(128) disc_kernel(const float* __restrict__ src,
                                                   const float* __restrict__ src_knn,
                                                   const int* __restrict__ src_idx,
                                                   const float* __restrict__ W1, const float* __restrict__ b1,
                                                   const float* __restrict__ W2, const float* __restrict__ b2,
                                                   const float* __restrict__ W3, const float* __restrict__ b3) {
    __shared__ float sW1[HD1 * 6];
    __shared__ float sb1[HD1];
    __shared__ float sfv[KK][6];
    __shared__ __align__(16) float h1a[KK][HD1];   // 4 KB
    __shared__ float partial[KK][4];

    int row = blockIdx.x;
    int b = row / NP, n = row % NP;
    int tid = threadIdx.x;     // = e in 0..127
    int lane = tid & 31, wid = tid >> 5;

    float4 w2v[16];
    const float4* w2g = (const float4*)(W2 + tid * HD1);
    #pragma unroll
    for (int i = 0; i < 16; i++) w2v[i] = w2g[i];
    float b2e = b2[tid];
    float w3e = W3[tid];
    float bias3 = b3[0];

    for (int i = tid; i < HD1 * 6; i += 128) sW1[i] = W1[i];
    if (tid < HD1) sb1[tid] = b1[tid];

    if (tid < KK * 6) {
        int k = tid / 6, c = tid % 6;
        int m2 = src_idx[(size_t)row * KK + k];
        if (c < 3)
            sfv[k][c] = d_src_corr[(b * 3 + c) * NP + n] - d_src_corr[(b * 3 + c) * NP + m2];
        else {
            int cc = c - 3;
            sfv[k][c] = src[(size_t)(b * 3 + cc) * NP + n]
                      - src_knn[((size_t)row * KK + k) * 3 + cc];
        }
    }
    __syncthreads();

    #pragma unroll
    for (int u = 0; u < 8; u++) {
        int idx = tid + u * 128;
        int k = idx >> 6, j = idx & 63;
        float a = sb1[j];
        #pragma unroll
        for (int c = 0; c < 6; c++) a = fmaf(sW1[j * 6 + c], sfv[k][c], a);
        h1a[k][j] = fmaxf(a, 0.f);
    }
    __syncthreads();

    #pragma unroll 2
    for (int k = 0; k < KK; k++) {
        const float4* h1v = (const float4*)h1a[k];
        float a2 = b2e;
        #pragma unroll
        for (int i = 0; i < 16; i++) {
            float4 h = h1v[i];
            a2 = fmaf(w2v[i].x, h.x, a2);
            a2 = fmaf(w2v[i].y, h.y, a2);
            a2 = fmaf(w2v[i].z, h.z, a2);
            a2 = fmaf(w2v[i].w, h.w, a2);
        }
        a2 = fmaxf(a2, 0.f);
        float s = w3e * a2;
        #pragma unroll
        for (int o = 16; o > 0; o >>= 1) s += __shfl_down_sync(0xffffffffu, s, o);
        if (lane == 0) partial[k][wid] = s;
    }
    __syncthreads();

    if (tid < KK) {
        float s = partial[tid][0] + partial[tid][1] + partial[tid][2] + partial[tid][3] + bias3;
        #pragma unroll
        for (int o = 8; o > 0; o >>= 1) s = fmaxf(s, __shfl_down_sync(0xffffu, s, o));
        if (tid == 0) d_smax[row] = s;
    }
}

// ---------------------------------------------------------------------------
// 5. weight = softmax(smax) over N, per batch
// ---------------------------------------------------------------------------
__global__ void wsoftmax_kernel() {
    int b = blockIdx.x, tid = threadIdx.x;   // 256
    __shared__ float sh[NP];
    __shared__ float red[256];
    const float* sp = d_smax + (size_t)b * NP;
    float lmax = -FLT_MAX;
    for (int n = tid; n < NP; n += 256) { float v = sp[n]; sh[n] = v; lmax = fmaxf(lmax, v); }
    red[tid] = lmax; __syncthreads();
    for (int s = 128; s > 0; s >>= 1) { if (tid < s) red[tid] = fmaxf(red[tid], red[tid + s]); __syncthreads(); }
    float mx = red[0]; __syncthreads();
    float lsum = 0.f;
    for (int n = tid; n < NP; n += 256) { float e = expf(sh[n] - mx); sh[n] = e; lsum += e; }
    red[tid] = lsum; __syncthreads();
    for (int s = 128; s > 0; s >>= 1) { if (tid < s) red[tid] += red[tid + s]; __syncthreads(); }
    float inv = 1.f / red[0];
    float* wp = d_weight + (size_t)b * NP;
    for (int n = tid; n < NP; n += 256) wp[n] = sh[n] * inv;
}

// ---------------------------------------------------------------------------
// 6. exact stable top-K by rank counting, 8 blocks per batch
// ---------------------------------------------------------------------------
__global__ void topk_kernel() {
    int blk = blockIdx.x;
    int b = blk >> 3, seg = blk & 7;
    int tid = threadIdx.x;                   // 256
    __shared__ float w[NP];
    for (int i = tid; i < NP; i += 256) w[i] = d_weight[b * NP + i];
    __syncthreads();
    int cand = seg * 256 + tid;
    float v = w[cand];
    int rank = 0;
    for (int j = 0; j < NP; j++) {
        float u = w[j];
        rank += (u > v) || (u == v && j < cand);
    }
    if (rank < KEY) d_topi[b * KEY + rank] = cand;
}

// ---------------------------------------------------------------------------
// 7. rigid: single-pass raw moments -> H; 3x3 SVD (double Jacobi), R, t
// ---------------------------------------------------------------------------
__global__ void rigid_kernel(const float* __restrict__ src, float* __restrict__ out) {
    int b = blockIdx.x, tid = threadIdx.x;   // 256 threads
    int lane = tid & 31, wid = tid >> 5;
    __shared__ double pm[8][16];

    double mom[16];
    #pragma unroll
    for (int i = 0; i < 16; i++) mom[i] = 0.0;
    for (int n = tid; n < NP; n += 256) {
        double w = (double)d_weight[b * NP + n];
        double s0 = (double)src[(size_t)(b * 3 + 0) * NP + n];
        double s1 = (double)src[(size_t)(b * 3 + 1) * NP + n];
        double s2 = (double)src[(size_t)(b * 3 + 2) * NP + n];
        double c0 = (double)d_src_corr[(b * 3 + 0) * NP + n];
        double c1 = (double)d_src_corr[(b * 3 + 1) * NP + n];
        double c2 = (double)d_src_corr[(b * 3 + 2) * NP + n];
        mom[0] += w;
        mom[1] += w * s0; mom[2] += w * s1; mom[3] += w * s2;
        mom[4] += w * c0; mom[5] += w * c1; mom[6] += w * c2;
        double ws0 = w * s0, ws1 = w * s1, ws2 = w * s2;
        mom[7]  += ws0 * c0; mom[8]  += ws0 * c1; mom[9]  += ws0 * c2;
        mom[10] += ws1 * c0; mom[11] += ws1 * c1; mom[12] += ws1 * c2;
        mom[13] += ws2 * c0; mom[14] += ws2 * c1; mom[15] += ws2 * c2;
    }
    #pragma unroll
    for (int i = 0; i < 16; i++) {
        double v = mom[i];
        #pragma unroll
        for (int o = 16; o > 0; o >>= 1) v += __shfl_down_sync(0xffffffffu, v, o);
        if (lane == 0) pm[wid][i] = v;
    }
    __syncthreads();

    if (tid == 0) {
        double M16[16];
        #pragma unroll
        for (int i = 0; i < 16; i++) {
            double s = pm[0][i];
            #pragma unroll
            for (int wv = 1; wv < 8; wv++) s += pm[wv][i];
            M16[i] = s;
        }
        double SW = M16[0];
        double cs[3] = {M16[1] / SW, M16[2] / SW, M16[3] / SW};
        double ct[3] = {M16[4] / SW, M16[5] / SW, M16[6] / SW};
        double Hm[3][3];
        for (int i = 0; i < 3; i++)
            for (int j = 0; j < 3; j++)
                Hm[i][j] = M16[7 + i * 3 + j] / SW - cs[i] * ct[j];

        double A[3][3], V[3][3] = {{1,0,0},{0,1,0},{0,0,1}};
        for (int i = 0; i < 3; i++)
            for (int j = 0; j < 3; j++) {
                double s = 0;
                for (int k = 0; k < 3; k++) s += Hm[k][i] * Hm[k][j];
                A[i][j] = s;
            }
        for (int sweep = 0; sweep < 8; sweep++) {
            for (int pp = 0; pp < 3; pp++) {
                int p = (pp == 0) ? 0 : (pp == 1) ? 0 : 1;
                int q = (pp == 0) ? 1 : (pp == 1) ? 2 : 2;
                double apq = A[p][q];
                if (fabs(apq) < 1e-300) continue;
                double tau = (A[q][q] - A[p][p]) / (2.0 * apq);
                double t = ((tau >= 0) ? 1.0 : -1.0) / (fabs(tau) + sqrt(1.0 + tau * tau));
                double c = 1.0 / sqrt(1.0 + t * t), s = t * c;
                for (int k = 0; k < 3; k++) {
                    double akp = A[k][p], akq = A[k][q];
                    A[k][p] = c * akp - s * akq;
                    A[k][q] = s * akp + c * akq;
                }
                for (int k = 0; k < 3; k++) {
                    double apk = A[p][k], aqk = A[q][k];
                    A[p][k] = c * apk - s * aqk;
                    A[q][k] = s * apk + c * aqk;
                }
                for (int k = 0; k < 3; k++) {
                    double vkp = V[k][p], vkq = V[k][q];
                    V[k][p] = c * vkp - s * vkq;
                    V[k][q] = s * vkp + c * vkq;
                }
            }
        }
        double eig[3] = {A[0][0], A[1][1], A[2][2]};
        for (int i = 0; i < 2; i++)
            for (int j = i + 1; j < 3; j++)
                if (eig[j] > eig[i]) {
                    double tmp = eig[i]; eig[i] = eig[j]; eig[j] = tmp;
                    for (int k = 0; k < 3; k++) { double tv = V[k][i]; V[k][i] = V[k][j]; V[k][j] = tv; }
                }
        double sig[3], U[3][3];
        for (int k = 0; k < 3; k++) sig[k] = sqrt(fmax(eig[k], 0.0));
        for (int k = 0; k < 3; k++) {
            double u[3];
            for (int i = 0; i < 3; i++)
                u[i] = Hm[i][0] * V[0][k] + Hm[i][1] * V[1][k] + Hm[i][2] * V[2][k];
            double inv = (sig[k] > 1e-12 * (sig[0] + 1e-300)) ? 1.0 / sig[k] : 0.0;
            for (int i = 0; i < 3; i++) U[i][k] = u[i] * inv;
        }
        if (sig[2] <= 1e-10 * (sig[0] + 1e-300)) {
            U[0][2] = U[1][0] * U[2][1] - U[2][0] * U[1][1];
            U[1][2] = U[2][0] * U[0][1] - U[0][0] * U[2][1];
            U[2][2] = U[0][0] * U[1][1] - U[1][0] * U[0][1];
        }
        double detH = Hm[0][0] * (Hm[1][1] * Hm[2][2] - Hm[1][2] * Hm[2][1])
                    - Hm[0][1] * (Hm[1][0] * Hm[2][2] - Hm[1][2] * Hm[2][0])
                    + Hm[0][2] * (Hm[1][0] * Hm[2][1] - Hm[1][1] * Hm[2][0]);
        double dsign = (detH >= 0) ? 1.0 : -1.0;
        double R[3][3];
        for (int i = 0; i < 3; i++)
            for (int j = 0; j < 3; j++)
                R[i][j] = V[i][0] * U[j][0] + V[i][1] * U[j][1] + dsign * V[i][2] * U[j][2];
        double tv3[3];
        for (int c = 0; c < 3; c++)
            tv3[c] = ct[c] - (R[c][0] * cs[0] + R[c][1] * cs[1] + R[c][2] * cs[2]);
        for (int i = 0; i < 3; i++)
            for (int j = 0; j < 3; j++) {
                float rv = (float)R[i][j];
                out[OUT_R + b * 9 + i * 3 + j] = rv;
                d_Rm[b * 9 + i * 3 + j] = rv;
            }
        for (int c = 0; c < 3; c++) {
            float tvf = (float)tv3[c];
            out[OUT_T + b * 3 + c] = tvf;
            d_tv[b * 3 + c] = tvf;
        }
    }
}

// ---------------------------------------------------------------------------
// 8. keypoint / knn outputs
// ---------------------------------------------------------------------------
__global__ void outputs_kernel(const float* __restrict__ src,
                               const int* __restrict__ src_idx,
                               float* __restrict__ out) {
    int idx = blockIdx.x * blockDim.x + threadIdx.x;   // b*KEY + j
    if (idx >= BB * KEY) return;
    int b = idx / KEY, j = idx % KEY;
    int n = d_topi[idx];
    float R[9], t[3];
    #pragma unroll
    for (int i = 0; i < 9; i++) R[i] = d_Rm[b * 9 + i];
    #pragma unroll
    for (int i = 0; i < 3; i++) t[i] = d_tv[b * 3 + i];

    float sp[3], cp[3], st[3];
    #pragma unroll
    for (int c = 0; c < 3; c++) {
        sp[c] = src[(size_t)(b * 3 + c) * NP + n];
        cp[c] = d_src_corr[(b * 3 + c) * NP + n];
    }
    #pragma unroll
    for (int c = 0; c < 3; c++) {
        st[c] = fmaf(R[c*3+0], sp[0], fmaf(R[c*3+1], sp[1], fmaf(R[c*3+2], sp[2], t[c])));
        out[OUT_SKP + (b * 3 + c) * KEY + j] = sp[c];
        out[OUT_TKP + (b * 3 + c) * KEY + j] = cp[c];
    }
    const int* idxp = src_idx + ((size_t)b * NP + n) * KK;
    for (int k = 0; k < KK; k++) {
        int m2 = idxp[k];
        float sp2[3], cp2[3];
        #pragma unroll
        for (int c = 0; c < 3; c++) {
            sp2[c] = src[(size_t)(b * 3 + c) * NP + m2];
            cp2[c] = d_src_corr[(b * 3 + c) * NP + m2];
        }
        #pragma unroll
        for (int c = 0; c < 3; c++) {
            float st2 = fmaf(R[c*3+0], sp2[0], fmaf(R[c*3+1], sp2[1], fmaf(R[c*3+2], sp2[2], t[c])));
            out[OUT_SKNN + ((size_t)(b * 3 + c) * KEY + j) * KK + k] = st[c] - st2;
            out[OUT_TKNN + ((size_t)(b * 3 + c) * KEY + j) * KK + k] = cp[c] - cp2[c];
        }
    }
}

// ---------------------------------------------------------------------------
// 9. loss = mean(-log(rowmax(rmm)[topi] + 1e-15))
// ---------------------------------------------------------------------------
__global__ void loss_kernel(float* __restrict__ out) {
    __shared__ double red[256];
    int tid = threadIdx.x;
    double acc = 0.0;
    for (int idx = tid; idx < BB * KEY; idx += 256) {
        int b = idx / KEY;
        int n = d_topi[idx];
        double p = (double)d_rowmax[b * NP + n];
        acc += -log(p + 1e-15);
    }
    red[tid] = acc; __syncthreads();
    for (int s = 128; s > 0; s >>= 1) { if (tid < s) red[tid] += red[tid + s]; __syncthreads(); }
    if (tid == 0) out[OUT_LOSS] = (float)(red[0] / (double)(BB * KEY));
}

// ---------------------------------------------------------------------------
extern "C" void kernel_launch(void* const* d_in, const int* in_sizes, int n_in,
                              void* d_out, int out_size) {
    const float* src      = (const float*)d_in[0];
    const float* tgt      = (const float*)d_in[1];
    const float* semb     = (const float*)d_in[2];
    const float* temb     = (const float*)d_in[3];
    const float* src_knn  = (const float*)d_in[4];
    // d_in[5] = tgt_knn (unused by the reference forward)
    const float* W1       = (const float*)d_in[6];
    const float* b1       = (const float*)d_in[7];
    const float* W2       = (const float*)d_in[8];
    const float* b2       = (const float*)d_in[9];
    const float* W3       = (const float*)d_in[10];
    const float* b3       = (const float*)d_in[11];
    const int*   src_idx  = (const int*)d_in[12];
    const int*   src_idx1 = (const int*)d_in[13];
    const int*   idx2     = (const int*)d_in[14];
    float* out = (float*)d_out;

    norms_kernel<<<(BB * (NP + MP) + 255) / 256, 256>>>(semb, temb);       // launch 0
    presplit_kernel<<<(2 * XN + 255) / 256, 256>>>(semb, temb);            // launch 1

    static int smem_set = 0;
    const int GEMM_SMEM = 8 * STG * (int)sizeof(float);   // 67,584 B
    if (!smem_set) {
        cudaFuncSetAttribute(dist_gemm_tc, cudaFuncAttributeMaxDynamicSharedMemorySize, GEMM_SMEM);
        smem_set = 1;
    }
    dim3 gg(MP / 128, NP / 128, BB);
    dist_gemm_tc<<<gg, 256, GEMM_SMEM>>>();                                // launch 2

    rmm_kernel<<<BB * NP, 256>>>(src_idx1, idx2, tgt);                     // launch 3 <- profiled
    disc_kernel<<<BB * NP, 128>>>(src, src_knn, src_idx, W1, b1, W2, b2, W3, b3);
    wsoftmax_kernel<<<BB, 256>>>();
    topk_kernel<<<BB * 8, 256>>>();
    rigid_kernel<<<BB, 256>>>(src, out);
    outputs_kernel<<<(BB * KEY + 255) / 256, 256>>>(src, src_idx, out);
    loss_kernel<<<1, 256>>>(out);
}

// round 10
// speedup vs baseline: 1.0957x; 1.0957x over previous
#include <cuda_runtime.h>
#include <math.h>
#include <float.h>
#include <stdint.h>

// Problem constants
#define BB  2
#define NP  2048
#define MP  2048
#define CCH 512
#define KK  16
#define KK1 8
#define KEY 1024
#define HD1 64
#define HD2 128

// Output layout (flattened tuple, in order)
#define OUT_R    0
#define OUT_T    18
#define OUT_SKP  24
#define OUT_TKP  (OUT_SKP  + BB*3*KEY)        // 6168
#define OUT_SKNN (OUT_TKP  + BB*3*KEY)        // 12312
#define OUT_TKNN (OUT_SKNN + BB*3*KEY*KK)     // 110616
#define OUT_LOSS (OUT_TKNN + BB*3*KEY*KK)     // 208920

// Scratch (static device globals; no allocation at runtime)
__device__ float d_dist[BB*NP*MP];
__device__ float d_xx[BB*NP];
__device__ float d_yy[BB*MP];
__device__ float d_src_corr[BB*3*NP];
__device__ float d_rowmax[BB*NP];
__device__ float d_smax[BB*NP];
__device__ float d_weight[BB*NP];
__device__ int   d_topi[BB*KEY];
__device__ float d_Rm[BB*9];
__device__ float d_tv[BB*3];

// ---------------------------------------------------------------------------
// 1. squared norms of embedding columns; block = 64 columns x 4 k-segments
// ---------------------------------------------------------------------------
__global__ void norms_kernel(const float* __restrict__ X, const float* __restrict__ Y) {
    __shared__ float part[4][64];
    int tid = threadIdx.x;               // 256
    int nl = tid & 63, cseg = tid >> 6;  // 64 cols, 4 segments
    int col = blockIdx.x * 64 + nl;      // 0..8191

    const float* p;
    if (col < BB * NP) {
        int b = col / NP, n = col % NP;
        p = X + (size_t)b * CCH * NP + n;
    } else {
        int idy = col - BB * NP;
        int b = idy / MP, m = idy % MP;
        p = Y + (size_t)b * CCH * MP + m;
    }
    float s = 0.f;
    int c0 = cseg * (CCH / 4);
    #pragma unroll 8
    for (int c = 0; c < CCH / 4; c++) {
        float v = p[(size_t)(c0 + c) * NP];
        s = fmaf(v, v, s);
    }
    part[cseg][nl] = s;
    __syncthreads();
    if (cseg == 0) {
        float r = part[0][nl] + part[1][nl] + part[2][nl] + part[3][nl];
        if (col < BB * NP) d_xx[col] = r;
        else d_yy[col - BB * NP] = r;
    }
}

// ---------------------------------------------------------------------------
// 2. dist GEMM on tensor cores: 3xTF32 mma.sync.m16n8k8, 2 CTAs/SM (R6 config)
// ---------------------------------------------------------------------------
#define SA 132
#define STAGE (32*SA)

__device__ __forceinline__ void cp_async16(uint32_t dst, const void* src) {
    asm volatile("cp.async.cg.shared.global [%0], [%1], 16;\n"
                 :: "r"(dst), "l"(src));
}
__device__ __forceinline__ void split_tf32(float x, uint32_t& hi, uint32_t& lo) {
    asm("cvt.rna.tf32.f32 %0, %1;" : "=r"(hi) : "f"(x));
    float r = x - __uint_as_float(hi);
    asm("cvt.rna.tf32.f32 %0, %1;" : "=r"(lo) : "f"(r));
}
__device__ __forceinline__ void mma_tf32(float c[4],
                                         uint32_t a0, uint32_t a1, uint32_t a2, uint32_t a3,
                                         uint32_t b0, uint32_t b1) {
    asm volatile("mma.sync.aligned.m16n8k8.row.col.f32.tf32.tf32.f32 "
                 "{%0,%1,%2,%3}, {%4,%5,%6,%7}, {%8,%9}, {%0,%1,%2,%3};"
                 : "+f"(c[0]), "+f"(c[1]), "+f"(c[2]), "+f"(c[3])
                 : "r"(a0), "r"(a1), "r"(a2), "r"(a3), "r"(b0), "r"(b1));
}

extern __shared__ float dynsmem[];

__global__ void __launch_bounds__(256, 2) dist_gemm_tc(const float* __restrict__ X,
                                                       const float* __restrict__ Y) {
    int b  = blockIdx.z;
    int n0 = blockIdx.y * 128;
    int m0 = blockIdx.x * 128;
    const float* Xb = X + (size_t)b * CCH * NP;
    const float* Yb = Y + (size_t)b * CCH * MP;
    int tid  = threadIdx.x;
    int w    = tid >> 5;
    int lane = tid & 31;
    int g = lane >> 2;
    int q = lane & 3;
    int wn = w & 1;
    int wm = w >> 1;
    int nbw = wn * 64;
    int mbw = wm * 32;

    float* As = dynsmem;
    float* Bs = dynsmem + 2 * STAGE;
    uint32_t sbase = (uint32_t)__cvta_generic_to_shared(dynsmem);

    float c[4][4][4];
    #pragma unroll
    for (int i = 0; i < 4; i++)
        #pragma unroll
        for (int j = 0; j < 4; j++)
            #pragma unroll
            for (int r = 0; r < 4; r++) c[i][j][r] = 0.f;

    #define PREFETCH(T, S)                                                      \
        {                                                                       \
            int c0_ = (T) * 32;                                                 \
            _Pragma("unroll")                                                   \
            for (int i_ = 0; i_ < 4; i_++) {                                    \
                int f_ = tid + i_ * 256;                                        \
                int kk_ = f_ >> 5, c4_ = (f_ & 31) * 4;                         \
                uint32_t da_ = sbase + (uint32_t)(((S) * STAGE + kk_ * SA + c4_) * 4); \
                cp_async16(da_, Xb + (size_t)(c0_ + kk_) * NP + n0 + c4_);      \
                uint32_t db_ = sbase + (uint32_t)(((2 + (S)) * STAGE + kk_ * SA + c4_) * 4); \
                cp_async16(db_, Yb + (size_t)(c0_ + kk_) * MP + m0 + c4_);      \
            }                                                                   \
            asm volatile("cp.async.commit_group;");                             \
        }

    PREFETCH(0, 0);

    const int NT = CCH / 32;
    for (int t = 0; t < NT; t++) {
        if (t + 1 < NT) {
            PREFETCH(t + 1, (t + 1) & 1);
            asm volatile("cp.async.wait_group 1;");
        } else {
            asm volatile("cp.async.wait_group 0;");
        }
        __syncthreads();

        const float* Ast = As + (t & 1) * STAGE;
        const float* Bst = Bs + (t & 1) * STAGE;

        #pragma unroll
        for (int ks = 0; ks < 4; ks++) {
            int kb = ks * 8;
            uint32_t bh[4][2], bl[4][2];
            #pragma unroll
            for (int j = 0; j < 4; j++) {
                int mb = mbw + j * 8 + g;
                float b0 = Bst[(kb + q) * SA + mb];
                float b1 = Bst[(kb + q + 4) * SA + mb];
                split_tf32(b0, bh[j][0], bl[j][0]);
                split_tf32(b1, bh[j][1], bl[j][1]);
            }
            #pragma unroll
            for (int i = 0; i < 4; i++) {
                int nb = nbw + i * 16 + g;
                float a0 = Ast[(kb + q) * SA + nb];
                float a1 = Ast[(kb + q) * SA + nb + 8];
                float a2 = Ast[(kb + q + 4) * SA + nb];
                float a3 = Ast[(kb + q + 4) * SA + nb + 8];
                uint32_t ah0, al0, ah1, al1, ah2, al2, ah3, al3;
                split_tf32(a0, ah0, al0);
                split_tf32(a1, ah1, al1);
                split_tf32(a2, ah2, al2);
                split_tf32(a3, ah3, al3);
                #pragma unroll
                for (int j = 0; j < 4; j++) {
                    mma_tf32(c[i][j], al0, al1, al2, al3, bh[j][0], bh[j][1]);
                    mma_tf32(c[i][j], ah0, ah1, ah2, ah3, bl[j][0], bl[j][1]);
                    mma_tf32(c[i][j], ah0, ah1, ah2, ah3, bh[j][0], bh[j][1]);
                }
            }
        }
        __syncthreads();
    }
    #undef PREFETCH

    int bN = b * NP, bM = b * MP;
    #pragma unroll
    for (int i = 0; i < 4; i++) {
        int ng0 = n0 + nbw + i * 16 + g;
        int ng1 = ng0 + 8;
        float xv0 = d_xx[bN + ng0];
        float xv1 = d_xx[bN + ng1];
        float* r0 = d_dist + (size_t)(bN + ng0) * MP;
        float* r1 = d_dist + (size_t)(bN + ng1) * MP;
        #pragma unroll
        for (int j = 0; j < 4; j++) {
            int mg = m0 + mbw + j * 8 + 2 * q;
            float y0 = d_yy[bM + mg];
            float y1 = d_yy[bM + mg + 1];
            float2 v0 = make_float2(xv0 - 2.f * c[i][j][0] + y0,
                                    xv0 - 2.f * c[i][j][1] + y1);
            float2 v1 = make_float2(xv1 - 2.f * c[i][j][2] + y0,
                                    xv1 - 2.f * c[i][j][3] + y1);
            *(float2*)(r0 + mg) = v0;
            *(float2*)(r1 + mg) = v1;
        }
    }
}

// ---------------------------------------------------------------------------
// block-sum reduction (shfl + 8-entry combine)
// ---------------------------------------------------------------------------
__device__ __forceinline__ float bred_sumf(float v, float* red8, int tid) {
    #pragma unroll
    for (int o = 16; o > 0; o >>= 1) v += __shfl_down_sync(0xffffffffu, v, o);
    __syncthreads();
    if ((tid & 31) == 0) red8[tid >> 5] = v;
    __syncthreads();
    float r = red8[0];
    #pragma unroll
    for (int i = 1; i < 8; i++) r += red8[i];
    return r;
}

// ---------------------------------------------------------------------------
// 3. fused: per-row score softmaxes -> T -> S -> refined -> rmm softmax ->
//    src_corr GEMV + row max. scores/T/rmm never hit global memory.
// ---------------------------------------------------------------------------
__global__ void rmm_kernel(const int* __restrict__ idx1,
                           const int* __restrict__ idx2,
                           const float* __restrict__ tgt) {
    int row = blockIdx.x;                 // b*NP + n
    int b = row / NP, n = row % NP;
    int tid = threadIdx.x;                // 256
    __shared__ float shT[MP];
    __shared__ float red8[8];
    __shared__ float red4[8][4];

    const int* ip1 = idx1 + (size_t)row * KK1;
    float Tr[8] = {0.f,0.f,0.f,0.f,0.f,0.f,0.f,0.f};
    #pragma unroll 1
    for (int j = 1; j < 8; j++) {
        const float4* dj = (const float4*)(d_dist + ((size_t)b * NP + ip1[j]) * MP);
        float4 v0 = dj[tid];
        float4 v1 = dj[tid + 256];
        float e[8];
        e[0] = __expf(-v0.x); e[1] = __expf(-v0.y);
        e[2] = __expf(-v0.z); e[3] = __expf(-v0.w);
        e[4] = __expf(-v1.x); e[5] = __expf(-v1.y);
        e[6] = __expf(-v1.z); e[7] = __expf(-v1.w);
        float lsum = (e[0] + e[1]) + (e[2] + e[3]) + (e[4] + e[5]) + (e[6] + e[7]);
        float inv = 1.f / bred_sumf(lsum, red8, tid);
        #pragma unroll
        for (int r = 0; r < 8; r++) Tr[r] = fmaf(e[r], inv, Tr[r]);
    }
    float4* shT4 = (float4*)shT;
    shT4[tid]       = make_float4(Tr[0], Tr[1], Tr[2], Tr[3]);
    shT4[tid + 256] = make_float4(Tr[4], Tr[5], Tr[6], Tr[7]);
    __syncthreads();

    const float* drow = d_dist + (size_t)row * MP;
    const int4* i2v = (const int4*)(idx2 + (size_t)b * MP * KK1);
    float r[8];
    float lsum = 0.f;
    #pragma unroll
    for (int it = 0; it < 8; it++) {
        int m = tid + it * 256;
        int4 a = i2v[2 * m], b4 = i2v[2 * m + 1];
        float S = shT[a.y] + shT[a.z] + shT[a.w]
                + shT[b4.x] + shT[b4.y] + shT[b4.z] + shT[b4.w];
        float rr = __expf(1.0f - S * (1.0f / 7.0f)) * drow[m];
        r[it] = __expf(-rr);
        lsum += r[it];
    }
    float inv = 1.f / bred_sumf(lsum, red8, tid);

    const float* t0 = tgt + (size_t)b * 3 * MP;
    float c0 = 0.f, c1 = 0.f, c2 = 0.f, lmax = -FLT_MAX;
    #pragma unroll
    for (int it = 0; it < 8; it++) {
        int m = tid + it * 256;
        float rv = r[it] * inv;
        c0 = fmaf(t0[m], rv, c0);
        c1 = fmaf(t0[MP + m], rv, c1);
        c2 = fmaf(t0[2 * MP + m], rv, c2);
        lmax = fmaxf(lmax, rv);
    }
    #pragma unroll
    for (int o = 16; o > 0; o >>= 1) {
        c0 += __shfl_down_sync(0xffffffffu, c0, o);
        c1 += __shfl_down_sync(0xffffffffu, c1, o);
        c2 += __shfl_down_sync(0xffffffffu, c2, o);
        lmax = fmaxf(lmax, __shfl_down_sync(0xffffffffu, lmax, o));
    }
    __syncthreads();
    if ((tid & 31) == 0) {
        int wid = tid >> 5;
        red4[wid][0] = c0; red4[wid][1] = c1; red4[wid][2] = c2; red4[wid][3] = lmax;
    }
    __syncthreads();
    if (tid == 0) {
        float s0 = 0.f, s1 = 0.f, s2 = 0.f, mx = -FLT_MAX;
        #pragma unroll
        for (int i = 0; i < 8; i++) {
            s0 += red4[i][0]; s1 += red4[i][1]; s2 += red4[i][2];
            mx = fmaxf(mx, red4[i][3]);
        }
        d_src_corr[(b * 3 + 0) * NP + n] = s0;
        d_src_corr[(b * 3 + 1) * NP + n] = s1;
        d_src_corr[(b * 3 + 2) * NP + n] = s2;
        d_rowmax[row] = mx;
    }
}

// ---------------------------------------------------------------------------
// 4. discriminator MLP: batched h1, barrier-free k-loop, 4-way ILP dot chains
// ---------------------------------------------------------------------------
__global__ void __launch_bounds__(128) disc_kernel(const float* __restrict__ src,
                                                   const float* __restrict__ src_knn,
                                                   const int* __restrict__ src_idx,
                                                   const float* __restrict__ W1, const float* __restrict__ b1,
                                                   const float* __restrict__ W2, const float* __restrict__ b2,
                                                   const float* __restrict__ W3, const float* __restrict__ b3) {
    __shared__ float sW1[HD1 * 6];
    __shared__ float sb1[HD1];
    __shared__ float sfv[KK][6];
    __shared__ __align__(16) float h1a[KK][HD1];   // 4 KB
    __shared__ float partial[KK][4];

    int row = blockIdx.x;
    int b = row / NP, n = row % NP;
    int tid = threadIdx.x;     // = e in 0..127
    int lane = tid & 31, wid = tid >> 5;

    float4 w2v[16];
    const float4* w2g = (const float4*)(W2 + tid * HD1);
    #pragma unroll
    for (int i = 0; i < 16; i++) w2v[i] = w2g[i];
    float b2e = b2[tid];
    float w3e = W3[tid];
    float bias3 = b3[0];

    for (int i = tid; i < HD1 * 6; i += 128) sW1[i] = W1[i];
    if (tid < HD1) sb1[tid] = b1[tid];

    if (tid < KK * 6) {
        int k = tid / 6, c = tid % 6;
        int m2 = src_idx[(size_t)row * KK + k];
        if (c < 3)
            sfv[k][c] = d_src_corr[(b * 3 + c) * NP + n] - d_src_corr[(b * 3 + c) * NP + m2];
        else {
            int cc = c - 3;
            sfv[k][c] = src[(size_t)(b * 3 + cc) * NP + n]
                      - src_knn[((size_t)row * KK + k) * 3 + cc];
        }
    }
    __syncthreads();

    #pragma unroll
    for (int u = 0; u < 8; u++) {
        int idx = tid + u * 128;
        int k = idx >> 6, j = idx & 63;
        float a = sb1[j];
        #pragma unroll
        for (int c = 0; c < 6; c++) a = fmaf(sW1[j * 6 + c], sfv[k][c], a);
        h1a[k][j] = fmaxf(a, 0.f);
    }
    __syncthreads();

    #pragma unroll 2
    for (int k = 0; k < KK; k++) {
        const float4* h1v = (const float4*)h1a[k];
        // 4 independent FMA chains (ILP), combined at the end
        float ax = b2e, ay = 0.f, az = 0.f, aw = 0.f;
        #pragma unroll
        for (int i = 0; i < 16; i++) {
            float4 h = h1v[i];
            ax = fmaf(w2v[i].x, h.x, ax);
            ay = fmaf(w2v[i].y, h.y, ay);
            az = fmaf(w2v[i].z, h.z, az);
            aw = fmaf(w2v[i].w, h.w, aw);
        }
        float a2 = fmaxf((ax + ay) + (az + aw), 0.f);
        float s = w3e * a2;
        #pragma unroll
        for (int o = 16; o > 0; o >>= 1) s += __shfl_down_sync(0xffffffffu, s, o);
        if (lane == 0) partial[k][wid] = s;
    }
    __syncthreads();

    if (tid < KK) {
        float s = partial[tid][0] + partial[tid][1] + partial[tid][2] + partial[tid][3] + bias3;
        #pragma unroll
        for (int o = 8; o > 0; o >>= 1) s = fmaxf(s, __shfl_down_sync(0xffffu, s, o));
        if (tid == 0) d_smax[row] = s;
    }
}

// ---------------------------------------------------------------------------
// 5. weight = softmax(smax) over N, per batch
// ---------------------------------------------------------------------------
__global__ void wsoftmax_kernel() {
    int b = blockIdx.x, tid = threadIdx.x;   // 256
    __shared__ float sh[NP];
    __shared__ float red[256];
    const float* sp = d_smax + (size_t)b * NP;
    float lmax = -FLT_MAX;
    for (int n = tid; n < NP; n += 256) { float v = sp[n]; sh[n] = v; lmax = fmaxf(lmax, v); }
    red[tid] = lmax; __syncthreads();
    for (int s = 128; s > 0; s >>= 1) { if (tid < s) red[tid] = fmaxf(red[tid], red[tid + s]); __syncthreads(); }
    float mx = red[0]; __syncthreads();
    float lsum = 0.f;
    for (int n = tid; n < NP; n += 256) { float e = expf(sh[n] - mx); sh[n] = e; lsum += e; }
    red[tid] = lsum; __syncthreads();
    for (int s = 128; s > 0; s >>= 1) { if (tid < s) red[tid] += red[tid + s]; __syncthreads(); }
    float inv = 1.f / red[0];
    float* wp = d_weight + (size_t)b * NP;
    for (int n = tid; n < NP; n += 256) wp[n] = sh[n] * inv;
}

// ---------------------------------------------------------------------------
// 6. exact stable top-K by rank counting, 8 blocks per batch
// ---------------------------------------------------------------------------
__global__ void topk_kernel() {
    int blk = blockIdx.x;
    int b = blk >> 3, seg = blk & 7;
    int tid = threadIdx.x;                   // 256
    __shared__ float w[NP];
    for (int i = tid; i < NP; i += 256) w[i] = d_weight[b * NP + i];
    __syncthreads();
    int cand = seg * 256 + tid;
    float v = w[cand];
    int rank = 0;
    for (int j = 0; j < NP; j++) {
        float u = w[j];
        rank += (u > v) || (u == v && j < cand);
    }
    if (rank < KEY) d_topi[b * KEY + rank] = cand;
}

// ---------------------------------------------------------------------------
// 7. rigid: single-pass raw moments -> H; 3x3 SVD (double Jacobi), R, t
// ---------------------------------------------------------------------------
__global__ void rigid_kernel(const float* __restrict__ src, float* __restrict__ out) {
    int b = blockIdx.x, tid = threadIdx.x;   // 256 threads
    int lane = tid & 31, wid = tid >> 5;
    __shared__ double pm[8][16];

    double mom[16];
    #pragma unroll
    for (int i = 0; i < 16; i++) mom[i] = 0.0;
    for (int n = tid; n < NP; n += 256) {
        double w = (double)d_weight[b * NP + n];
        double s0 = (double)src[(size_t)(b * 3 + 0) * NP + n];
        double s1 = (double)src[(size_t)(b * 3 + 1) * NP + n];
        double s2 = (double)src[(size_t)(b * 3 + 2) * NP + n];
        double c0 = (double)d_src_corr[(b * 3 + 0) * NP + n];
        double c1 = (double)d_src_corr[(b * 3 + 1) * NP + n];
        double c2 = (double)d_src_corr[(b * 3 + 2) * NP + n];
        mom[0] += w;
        mom[1] += w * s0; mom[2] += w * s1; mom[3] += w * s2;
        mom[4] += w * c0; mom[5] += w * c1; mom[6] += w * c2;
        double ws0 = w * s0, ws1 = w * s1, ws2 = w * s2;
        mom[7]  += ws0 * c0; mom[8]  += ws0 * c1; mom[9]  += ws0 * c2;
        mom[10] += ws1 * c0; mom[11] += ws1 * c1; mom[12] += ws1 * c2;
        mom[13] += ws2 * c0; mom[14] += ws2 * c1; mom[15] += ws2 * c2;
    }
    #pragma unroll
    for (int i = 0; i < 16; i++) {
        double v = mom[i];
        #pragma unroll
        for (int o = 16; o > 0; o >>= 1) v += __shfl_down_sync(0xffffffffu, v, o);
        if (lane == 0) pm[wid][i] = v;
    }
    __syncthreads();

    if (tid == 0) {
        double M16[16];
        #pragma unroll
        for (int i = 0; i < 16; i++) {
            double s = pm[0][i];
            #pragma unroll
            for (int wv = 1; wv < 8; wv++) s += pm[wv][i];
            M16[i] = s;
        }
        double SW = M16[0];
        double cs[3] = {M16[1] / SW, M16[2] / SW, M16[3] / SW};
        double ct[3] = {M16[4] / SW, M16[5] / SW, M16[6] / SW};
        double Hm[3][3];
        for (int i = 0; i < 3; i++)
            for (int j = 0; j < 3; j++)
                Hm[i][j] = M16[7 + i * 3 + j] / SW - cs[i] * ct[j];

        double A[3][3], V[3][3] = {{1,0,0},{0,1,0},{0,0,1}};
        for (int i = 0; i < 3; i++)
            for (int j = 0; j < 3; j++) {
                double s = 0;
                for (int k = 0; k < 3; k++) s += Hm[k][i] * Hm[k][j];
                A[i][j] = s;
            }
        for (int sweep = 0; sweep < 8; sweep++) {
            for (int pp = 0; pp < 3; pp++) {
                int p = (pp == 0) ? 0 : (pp == 1) ? 0 : 1;
                int q = (pp == 0) ? 1 : (pp == 1) ? 2 : 2;
                double apq = A[p][q];
                if (fabs(apq) < 1e-300) continue;
                double tau = (A[q][q] - A[p][p]) / (2.0 * apq);
                double t = ((tau >= 0) ? 1.0 : -1.0) / (fabs(tau) + sqrt(1.0 + tau * tau));
                double c = 1.0 / sqrt(1.0 + t * t), s = t * c;
                for (int k = 0; k < 3; k++) {
                    double akp = A[k][p], akq = A[k][q];
                    A[k][p] = c * akp - s * akq;
                    A[k][q] = s * akp + c * akq;
                }
                for (int k = 0; k < 3; k++) {
                    double apk = A[p][k], aqk = A[q][k];
                    A[p][k] = c * apk - s * aqk;
                    A[q][k] = s * apk + c * aqk;
                }
                for (int k = 0; k < 3; k++) {
                    double vkp = V[k][p], vkq = V[k][q];
                    V[k][p] = c * vkp - s * vkq;
                    V[k][q] = s * vkp + c * vkq;
                }
            }
        }
        double eig[3] = {A[0][0], A[1][1], A[2][2]};
        for (int i = 0; i < 2; i++)
            for (int j = i + 1; j < 3; j++)
                if (eig[j] > eig[i]) {
                    double tmp = eig[i]; eig[i] = eig[j]; eig[j] = tmp;
                    for (int k = 0; k < 3; k++) { double tv = V[k][i]; V[k][i] = V[k][j]; V[k][j] = tv; }
                }
        double sig[3], U[3][3];
        for (int k = 0; k < 3; k++) sig[k] = sqrt(fmax(eig[k], 0.0));
        for (int k = 0; k < 3; k++) {
            double u[3];
            for (int i = 0; i < 3; i++)
                u[i] = Hm[i][0] * V[0][k] + Hm[i][1] * V[1][k] + Hm[i][2] * V[2][k];
            double inv = (sig[k] > 1e-12 * (sig[0] + 1e-300)) ? 1.0 / sig[k] : 0.0;
            for (int i = 0; i < 3; i++) U[i][k] = u[i] * inv;
        }
        if (sig[2] <= 1e-10 * (sig[0] + 1e-300)) {
            U[0][2] = U[1][0] * U[2][1] - U[2][0] * U[1][1];
            U[1][2] = U[2][0] * U[0][1] - U[0][0] * U[2][1];
            U[2][2] = U[0][0] * U[1][1] - U[1][0] * U[0][1];
        }
        double detH = Hm[0][0] * (Hm[1][1] * Hm[2][2] - Hm[1][2] * Hm[2][1])
                    - Hm[0][1] * (Hm[1][0] * Hm[2][2] - Hm[1][2] * Hm[2][0])
                    + Hm[0][2] * (Hm[1][0] * Hm[2][1] - Hm[1][1] * Hm[2][0]);
        double dsign = (detH >= 0) ? 1.0 : -1.0;
        double R[3][3];
        for (int i = 0; i < 3; i++)
            for (int j = 0; j < 3; j++)
                R[i][j] = V[i][0] * U[j][0] + V[i][1] * U[j][1] + dsign * V[i][2] * U[j][2];
        double tv3[3];
        for (int c = 0; c < 3; c++)
            tv3[c] = ct[c] - (R[c][0] * cs[0] + R[c][1] * cs[1] + R[c][2] * cs[2]);
        for (int i = 0; i < 3; i++)
            for (int j = 0; j < 3; j++) {
                float rv = (float)R[i][j];
                out[OUT_R + b * 9 + i * 3 + j] = rv;
                d_Rm[b * 9 + i * 3 + j] = rv;
            }
        for (int c = 0; c < 3; c++) {
            float tvf = (float)tv3[c];
            out[OUT_T + b * 3 + c] = tvf;
            d_tv[b * 3 + c] = tvf;
        }
    }
}

// ---------------------------------------------------------------------------
// 8. keypoint / knn outputs
// ---------------------------------------------------------------------------
__global__ void outputs_kernel(const float* __restrict__ src,
                               const int* __restrict__ src_idx,
                               float* __restrict__ out) {
    int idx = blockIdx.x * blockDim.x + threadIdx.x;   // b*KEY + j
    if (idx >= BB * KEY) return;
    int b = idx / KEY, j = idx % KEY;
    int n = d_topi[idx];
    float R[9], t[3];
    #pragma unroll
    for (int i = 0; i < 9; i++) R[i] = d_Rm[b * 9 + i];
    #pragma unroll
    for (int i = 0; i < 3; i++) t[i] = d_tv[b * 3 + i];

    float sp[3], cp[3], st[3];
    #pragma unroll
    for (int c = 0; c < 3; c++) {
        sp[c] = src[(size_t)(b * 3 + c) * NP + n];
        cp[c] = d_src_corr[(b * 3 + c) * NP + n];
    }
    #pragma unroll
    for (int c = 0; c < 3; c++) {
        st[c] = fmaf(R[c*3+0], sp[0], fmaf(R[c*3+1], sp[1], fmaf(R[c*3+2], sp[2], t[c])));
        out[OUT_SKP + (b * 3 + c) * KEY + j] = sp[c];
        out[OUT_TKP + (b * 3 + c) * KEY + j] = cp[c];
    }
    const int* idxp = src_idx + ((size_t)b * NP + n) * KK;
    for (int k = 0; k < KK; k++) {
        int m2 = idxp[k];
        float sp2[3], cp2[3];
        #pragma unroll
        for (int c = 0; c < 3; c++) {
            sp2[c] = src[(size_t)(b * 3 + c) * NP + m2];
            cp2[c] = d_src_corr[(b * 3 + c) * NP + m2];
        }
        #pragma unroll
        for (int c = 0; c < 3; c++) {
            float st2 = fmaf(R[c*3+0], sp2[0], fmaf(R[c*3+1], sp2[1], fmaf(R[c*3+2], sp2[2], t[c])));
            out[OUT_SKNN + ((size_t)(b * 3 + c) * KEY + j) * KK + k] = st[c] - st2;
            out[OUT_TKNN + ((size_t)(b * 3 + c) * KEY + j) * KK + k] = cp[c] - cp2[c];
        }
    }
}

// ---------------------------------------------------------------------------
// 9. loss = mean(-log(rowmax(rmm)[topi] + 1e-15))
// ---------------------------------------------------------------------------
__global__ void loss_kernel(float* __restrict__ out) {
    __shared__ double red[256];
    int tid = threadIdx.x;
    double acc = 0.0;
    for (int idx = tid; idx < BB * KEY; idx += 256) {
        int b = idx / KEY;
        int n = d_topi[idx];
        double p = (double)d_rowmax[b * NP + n];
        acc += -log(p + 1e-15);
    }
    red[tid] = acc; __syncthreads();
    for (int s = 128; s > 0; s >>= 1) { if (tid < s) red[tid] += red[tid + s]; __syncthreads(); }
    if (tid == 0) out[OUT_LOSS] = (float)(red[0] / (double)(BB * KEY));
}

// ---------------------------------------------------------------------------
extern "C" void kernel_launch(void* const* d_in, const int* in_sizes, int n_in,
                              void* d_out, int out_size) {
    const float* src      = (const float*)d_in[0];
    const float* tgt      = (const float*)d_in[1];
    const float* semb     = (const float*)d_in[2];
    const float* temb     = (const float*)d_in[3];
    const float* src_knn  = (const float*)d_in[4];
    // d_in[5] = tgt_knn (unused by the reference forward)
    const float* W1       = (const float*)d_in[6];
    const float* b1       = (const float*)d_in[7];
    const float* W2       = (const float*)d_in[8];
    const float* b2       = (const float*)d_in[9];
    const float* W3       = (const float*)d_in[10];
    const float* b3       = (const float*)d_in[11];
    const int*   src_idx  = (const int*)d_in[12];
    const int*   src_idx1 = (const int*)d_in[13];
    const int*   idx2     = (const int*)d_in[14];
    float* out = (float*)d_out;

    norms_kernel<<<BB * (NP + MP) / 64, 256>>>(semb, temb);                // launch 0

    static int smem_set = 0;
    const int GEMM_SMEM = 4 * STAGE * (int)sizeof(float);   // 67,584 B
    if (!smem_set) {
        cudaFuncSetAttribute(dist_gemm_tc, cudaFuncAttributeMaxDynamicSharedMemorySize, GEMM_SMEM);
        smem_set = 1;
    }
    dim3 gg(MP / 128, NP / 128, BB);
    dist_gemm_tc<<<gg, 256, GEMM_SMEM>>>(semb, temb);                      // launch 1

    rmm_kernel<<<BB * NP, 256>>>(src_idx1, idx2, tgt);                     // launch 2
    disc_kernel<<<BB * NP, 128>>>(src, src_knn, src_idx, W1, b1, W2, b2, W3, b3); // launch 3 <- profiled
    wsoftmax_kernel<<<BB, 256>>>();
    topk_kernel<<<BB * 8, 256>>>();
    rigid_kernel<<<BB, 256>>>(src, out);
    outputs_kernel<<<(BB * KEY + 255) / 256, 256>>>(src, src_idx, out);
    loss_kernel<<<1, 256>>>(out);
}